// round 17
// baseline (speedup 1.0000x reference)
#include <cuda_runtime.h>
#include <cuda_fp16.h>
#include <cstdint>

// Problem constants (fixed by the reference)
#define NC   1024      // n_concepts (K)
#define NL   512       // n_lemmas   (N)
#define BTOT 4096      // batch      (M)
#define TSTEPS 50
#define GAMMA_C 0.95f
#define KAPPA_C 0.1f
#define FLOOR_C 1e-6f
#define A_SCALE   512.0f     // exact pow2; A pre-scaled into fp16 range
#define LO_SCALE  2048.0f    // exact pow2; lo planes scaled past fp16 subnormals

// ---------------- device scratch (no runtime alloc allowed) ----------------
__device__ __align__(1024) float g_drive[(size_t)BTOT * NL];    // 8 MB (512*drive)

// ---------------------------- PTX helpers (base ISA only) -------------------
__device__ __forceinline__ uint32_t smem_u32(const void* p) {
    uint32_t a;
    asm("{ .reg .u64 t; cvta.to.shared.u64 t, %1; cvt.u32.u64 %0, t; }" : "=r"(a) : "l"(p));
    return a;
}

#define LDSM4(r, addr) \
    asm volatile("ldmatrix.sync.aligned.m8n8.x4.shared.b16 {%0,%1,%2,%3}, [%4];" \
        : "=r"((r)[0]), "=r"((r)[1]), "=r"((r)[2]), "=r"((r)[3]) : "r"(addr))

#define MMAF32(d, a, b0, b1) \
    asm volatile("mma.sync.aligned.m16n8k16.row.col.f32.f16.f16.f32 " \
        "{%0,%1,%2,%3}, {%4,%5,%6,%7}, {%8,%9}, {%0,%1,%2,%3};" \
        : "+f"((d)[0]), "+f"((d)[1]), "+f"((d)[2]), "+f"((d)[3]) \
        : "r"((a)[0]), "r"((a)[1]), "r"((a)[2]), "r"((a)[3]), "r"(b0), "r"(b1))

// ------------------ HMMA GEMM with fully fused fp16 conversion --------------
// 512*drive = Ahi@Whi^T + [Ahi@Wlo^T + Alo@Whi^T]/2048, 3 terms fused per K64
// chunk. BOTH A and W are loaded as raw fp32 via LDG, split to fp16 hi/lo
// in-register, and STS'd into the next pipeline stage — no conversion kernels,
// no fp16 scratch, no extra gmem traffic (fp32 bytes == 2 fp16 planes).
// CTA 128x128, 8 warps (4M x 2N), 2-stage pipeline.
// Rows padded to 144 B (9*16, coprime 8 -> conflict-free ldmatrix).
#define ROW_B   144
#define TILE_B  (128 * ROW_B)          // 18432 B
#define STAGE_B (4 * TILE_B)           // Ahi, Alo, Whi, Wlo
#define STG     2
#define SMEM_TOT (STG * STAGE_B)       // 147456 B

__global__ __launch_bounds__(256, 1) void gemm_hmma_kernel(
    const float* __restrict__ Af32, const float* __restrict__ Wf32,
    float* __restrict__ D)
{
    extern __shared__ __align__(128) char smem[];
    const uint32_t sb = smem_u32(smem);
    const int tid = threadIdx.x, lane = tid & 31, wid = tid >> 5;
    const int wm = wid & 3, wn = wid >> 2;          // 4 x 2 warp grid
    const int m0 = blockIdx.y * 128, n0 = blockIdx.x * 128;

    float acc1[2][8][4], acc2[2][8][4];
    #pragma unroll
    for (int a = 0; a < 2; a++)
        #pragma unroll
        for (int b = 0; b < 8; b++)
            #pragma unroll
            for (int c = 0; c < 4; c++) { acc1[a][b][c] = 0.f; acc2[a][b][c] = 0.f; }

    // One tile chunk = 128 rows x 64 fp32 = 2048 float4 -> 2 batches of
    // 4 float4/thread. ci = b*1024 + i*256 + tid; r = ci>>4, c4 = ci&15.
    float4 v[4];
    auto ldg_batch = [&](const float* src, int base_row, int c, int b) {
        const int k0 = c << 6;
        #pragma unroll
        for (int i = 0; i < 4; i++) {
            const int ci = b * 1024 + i * 256 + tid;
            const int r = ci >> 4, c4 = ci & 15;
            v[i] = *reinterpret_cast<const float4*>(
                src + (size_t)(base_row + r) * NC + k0 + c4 * 4);
        }
    };
    // Split v -> hi/lo fp16 planes at stage s; hi_off selects A (0) or W (2T).
    auto cvt_sts = [&](uint32_t hi_off, float scale, int b, int s) {
        #pragma unroll
        for (int i = 0; i < 4; i++) {
            const int ci = b * 1024 + i * 256 + tid;
            const int r = ci >> 4, c4 = ci & 15;
            float f[4] = {v[i].x * scale, v[i].y * scale,
                          v[i].z * scale, v[i].w * scale};
            __half h[4], l[4];
            #pragma unroll
            for (int j = 0; j < 4; j++) {
                h[j] = __float2half_rn(f[j]);
                l[j] = __float2half_rn((f[j] - __half2float(h[j])) * LO_SCALE);
            }
            const uint32_t ro = s * STAGE_B + hi_off + r * ROW_B + c4 * 8;
            *reinterpret_cast<uint2*>(smem + ro)          = *reinterpret_cast<uint2*>(h);
            *reinterpret_cast<uint2*>(smem + ro + TILE_B) = *reinterpret_cast<uint2*>(l);
        }
    };

    auto mma_kk = [&](int s, int kk) {
        const uint32_t aHi = sb + s * STAGE_B;
        const uint32_t aLo = aHi + TILE_B;
        const uint32_t bHi = aHi + 2 * TILE_B;
        const uint32_t bLo = aHi + 3 * TILE_B;
        const uint32_t kb = kk * 32 + ((lane >> 4) << 4);
        uint32_t arh[2][4], arl[2][4], brh[4][4], brl[4][4];
        #pragma unroll
        for (int mi = 0; mi < 2; mi++) {
            const uint32_t ro = (wm * 32 + mi * 16 + (lane & 15)) * ROW_B + kb;
            LDSM4(arh[mi], aHi + ro);
            LDSM4(arl[mi], aLo + ro);
        }
        #pragma unroll
        for (int ni = 0; ni < 4; ni++) {
            const uint32_t ro = (wn * 64 + ni * 16 + (lane & 15)) * ROW_B + kb;
            LDSM4(brh[ni], bHi + ro);
            LDSM4(brl[ni], bLo + ro);
        }
        #pragma unroll
        for (int mi = 0; mi < 2; mi++)
            #pragma unroll
            for (int ni = 0; ni < 4; ni++) {
                MMAF32(acc1[mi][ni * 2],     arh[mi], brh[ni][0], brh[ni][2]);
                MMAF32(acc1[mi][ni * 2 + 1], arh[mi], brh[ni][1], brh[ni][3]);
                MMAF32(acc2[mi][ni * 2],     arh[mi], brl[ni][0], brl[ni][2]);
                MMAF32(acc2[mi][ni * 2 + 1], arh[mi], brl[ni][1], brl[ni][3]);
                MMAF32(acc2[mi][ni * 2],     arl[mi], brh[ni][0], brh[ni][2]);
                MMAF32(acc2[mi][ni * 2 + 1], arl[mi], brh[ni][1], brh[ni][3]);
            }
    };

    // ---- preamble: chunk 0 -> stage 0 (A then W) ----
    ldg_batch(Af32, m0, 0, 0); cvt_sts(0, A_SCALE, 0, 0);
    ldg_batch(Af32, m0, 0, 1); cvt_sts(0, A_SCALE, 1, 0);
    ldg_batch(Wf32, n0, 0, 0); cvt_sts(2 * TILE_B, 1.0f, 0, 0);
    ldg_batch(Wf32, n0, 0, 1); cvt_sts(2 * TILE_B, 1.0f, 1, 0);
    __syncthreads();

    const int NCHUNK = NC / 64;      // 16
    for (int c = 0; c < NCHUNK; ++c) {
        const int s = c & 1;
        const bool pf = (c + 1 < NCHUNK);
        if (pf) ldg_batch(Af32, m0, c + 1, 0);
        mma_kk(s, 0);
        if (pf) { cvt_sts(0, A_SCALE, 0, s ^ 1); ldg_batch(Af32, m0, c + 1, 1); }
        mma_kk(s, 1);
        if (pf) { cvt_sts(0, A_SCALE, 1, s ^ 1); ldg_batch(Wf32, n0, c + 1, 0); }
        mma_kk(s, 2);
        if (pf) { cvt_sts(2 * TILE_B, 1.0f, 0, s ^ 1); ldg_batch(Wf32, n0, c + 1, 1); }
        mma_kk(s, 3);
        if (pf) cvt_sts(2 * TILE_B, 1.0f, 1, s ^ 1);
        __syncthreads();
    }

    // ---- epilogue: drive = acc1 + acc2/2048 (still 512-scaled) ----
    const float inv_lo = 1.0f / LO_SCALE;
    #pragma unroll
    for (int mi = 0; mi < 2; mi++) {
        const int row = m0 + wm * 32 + mi * 16 + (lane >> 2);
        #pragma unroll
        for (int nj = 0; nj < 8; nj++) {
            const int col = n0 + wn * 64 + nj * 8 + (lane & 3) * 2;
            *reinterpret_cast<float2*>(&D[(size_t)row * NL + col]) =
                make_float2(fmaf(acc2[mi][nj][0], inv_lo, acc1[mi][nj][0]),
                            fmaf(acc2[mi][nj][1], inv_lo, acc1[mi][nj][1]));
            *reinterpret_cast<float2*>(&D[(size_t)(row + 8) * NL + col]) =
                make_float2(fmaf(acc2[mi][nj][2], inv_lo, acc1[mi][nj][2]),
                            fmaf(acc2[mi][nj][3], inv_lo, acc1[mi][nj][3]));
        }
    }
}

// ---------------------------------------------------------------------------
// Recurrence + selection: FOUR rows per warp (4 independent shfl chains hide
// SHFL latency; issue-bound). dv carries the 1/512 unscale.
// ---------------------------------------------------------------------------
__device__ __forceinline__ float tree_sum16(const float* a) {
    float t[8];
    #pragma unroll
    for (int j = 0; j < 8; j++) t[j] = a[j] + a[j + 8];
    #pragma unroll
    for (int j = 0; j < 4; j++) t[j] += t[j + 4];
    t[0] += t[2]; t[1] += t[3];
    return t[0] + t[1];
}

__global__ __launch_bounds__(128) void iterate_kernel(
    const float* __restrict__ D, const float* __restrict__ a0,
    float* __restrict__ out, int B, int write_aux)
{
    const int warp0 = (((blockIdx.x * blockDim.x + threadIdx.x) >> 5) << 2);
    const int lane = threadIdx.x & 31;
    if (warp0 >= B) return;

    const float inv_s = 1.0f / A_SCALE;
    float dv[4][16], a[4][16];
    #pragma unroll
    for (int r = 0; r < 4; r++) {
        const size_t ro = (size_t)(warp0 + r) * NL;
        #pragma unroll
        for (int i = 0; i < 16; i++) {
            dv[r][i] = D [ro + lane + 32 * i] * inv_s;
            a[r][i]  = a0[ro + lane + 32 * i];
        }
    }

    const float c1 = 1.0f + KAPPA_C;
    #pragma unroll 1
    for (int t = 0; t < TSTEPS; t++) {
        float p[4];
        #pragma unroll
        for (int r = 0; r < 4; r++) {
            #pragma unroll
            for (int i = 0; i < 16; i++)
                a[r][i] = fmaf(GAMMA_C, a[r][i], dv[r][i]);
            p[r] = tree_sum16(a[r]);
        }
        #pragma unroll
        for (int o = 16; o; o >>= 1) {
            #pragma unroll
            for (int r = 0; r < 4; r++)
                p[r] += __shfl_xor_sync(0xffffffffu, p[r], o);
        }
        #pragma unroll
        for (int r = 0; r < 4; r++) {
            const float kk = -KAPPA_C * p[r];
            #pragma unroll
            for (int i = 0; i < 16; i++)
                a[r][i] = fmaxf(fmaf(c1, a[r][i], kk), 0.f);
        }
    }

    #pragma unroll
    for (int r = 0; r < 4; r++) {
        float s = 0.f, m = -1.f;
        int mi = NL;
        #pragma unroll
        for (int i = 0; i < 16; i++) {
            float v = a[r][i];
            s += v;
            if (v > m) { m = v; mi = lane + 32 * i; }
        }
        #pragma unroll
        for (int o = 16; o; o >>= 1) {
            float om  = __shfl_xor_sync(0xffffffffu, m,  o);
            int   omi = __shfl_xor_sync(0xffffffffu, mi, o);
            float os  = __shfl_xor_sync(0xffffffffu, s,  o);
            s += os;
            if (om > m || (om == m && omi < mi)) { m = om; mi = omi; }
        }
        const size_t ro = (size_t)(warp0 + r) * NL;
        #pragma unroll
        for (int i = 0; i < 16; i++)
            out[ro + lane + 32 * i] = a[r][i];
        if (lane == 0 && write_aux) {
            const size_t base = (size_t)B * NL;
            out[base + warp0 + r]     = (float)mi;
            out[base + B + warp0 + r] = m / fmaxf(s * (1.0f / NL), FLOOR_C);
        }
    }
}

// ---------------------------------------------------------------------------
extern "C" void kernel_launch(void* const* d_in, const int* in_sizes, int n_in,
                              void* d_out, int out_size)
{
    const float* c_lex = (const float*)d_in[0];   // (B, 1024)
    const float* W     = (const float*)d_in[1];   // (512, 1024)
    const float* a0    = (const float*)d_in[2];   // (B, 512)
    float* out = (float*)d_out;

    const int B = in_sizes[0] / NC;               // 4096

    float* drive = nullptr;
    cudaGetSymbolAddress((void**)&drive, g_drive);

    // ---- phase 1: scaled drive via fp16 HMMA; A and W converted in-kernel --
    cudaFuncSetAttribute(gemm_hmma_kernel,
                         cudaFuncAttributeMaxDynamicSharedMemorySize, SMEM_TOT);
    dim3 ggrid(NL / 128, B / 128);   // (4, 32) = 128 CTAs, one wave
    gemm_hmma_kernel<<<ggrid, 256, SMEM_TOT>>>(c_lex, W, drive);

    // ---- phase 2: 50-step recurrence + selection (4 rows/warp) ----
    const int write_aux = (out_size >= B * NL + 2 * B) ? 1 : 0;
    const int nwarp = B / 4;                       // 1024 warps
    const int nblk = (nwarp * 32 + 127) / 128;     // 256 blocks of 128 thr
    iterate_kernel<<<nblk, 128>>>(drive, a0, out, B, write_aux);
}